// round 2
// baseline (speedup 1.0000x reference)
#include <cuda_runtime.h>
#include <math.h>

#define BB   4
#define C8   8
#define C16  16
#define FF   256
#define TN   2000
#define CHW  (FF*TN)
#define TWO_PI_F     6.283185307179586f
#define INV_TWO_PI_F 0.15915494309189535f

typedef unsigned long long ull;

__device__ float g_s1[BB*2*C16*CHW];
__device__ float g_s2[BB*2*C16*CHW];

__device__ __forceinline__ float mod2pi(float a) {
    return a - floorf(a * INV_TWO_PI_F) * TWO_PI_F;
}

// ---- f32x2 packed helpers (sm_103a: fma.rn.f32x2 is PTX-only) ----
__device__ __forceinline__ ull pk(float lo, float hi) {
    ull r; asm("mov.b64 %0,{%1,%2};" : "=l"(r) : "f"(lo), "f"(hi)); return r;
}
__device__ __forceinline__ void upk(ull v, float& lo, float& hi) {
    asm("mov.b64 {%0,%1},%2;" : "=f"(lo), "=f"(hi) : "l"(v));
}
__device__ __forceinline__ ull ffma2(ull a, ull b, ull c) {
    ull d; asm("fma.rn.f32x2 %0,%1,%2,%3;" : "=l"(d) : "l"(a), "l"(b), "l"(c)); return d;
}
__device__ __forceinline__ ull fmul2(ull a, ull b) {
    ull d; asm("mul.rn.f32x2 %0,%1,%2;" : "=l"(d) : "l"(a), "l"(b)); return d;
}
__device__ __forceinline__ ull ld64(const float* p) {
    return *reinterpret_cast<const ull*>(p);
}
__device__ __forceinline__ void st64(float* p, ull v) {
    *reinterpret_cast<ull*>(p) = v;
}

// ---------------------------------------------------------------------------
// Kernel A: cLog -> channel_shuffle (8->16) -> cAct.  2 timesteps per thread.
// ---------------------------------------------------------------------------
__global__ void kA(const float* __restrict__ x,
                   const float* __restrict__ wr, const float* __restrict__ wi,
                   const float* __restrict__ br, const float* __restrict__ bi)
{
    const int f = blockIdx.y;
    const int b = blockIdx.z;

    __shared__ ull swr2[C16*C8], swi2[C16*C8];
    __shared__ ull sbr2[C16], sbi2[C16];
    for (int i = threadIdx.x; i < C16*C8; i += blockDim.x) {
        float a = wr[f*C16*C8 + i]; swr2[i] = pk(a, a);
        float c = wi[f*C16*C8 + i]; swi2[i] = pk(c, c);
    }
    if (threadIdx.x < C16) {
        float a = br[f*C16 + threadIdx.x]; sbr2[threadIdx.x] = pk(a, a);
        float c = bi[f*C16 + threadIdx.x]; sbi2[threadIdx.x] = pk(c, c);
    }
    __syncthreads();

    const int tp = 2 * (blockIdx.x * blockDim.x + threadIdx.x);
    if (tp >= TN) return;
    const int off = f*TN + tp;

    ull lm2[C8], ph2[C8];
    #pragma unroll
    for (int c = 0; c < C8; c++) {
        ull xr = ld64(x + ((b*2+0)*C8 + c)*CHW + off);
        ull xi = ld64(x + ((b*2+1)*C8 + c)*CHW + off);
        float r0, r1, i0, i1;
        upk(xr, r0, r1); upk(xi, i0, i1);
        float l0 = 0.5f * __logf(fmaf(r0, r0, fmaf(i0, i0, 1e-12f)));
        float l1 = 0.5f * __logf(fmaf(r1, r1, fmaf(i1, i1, 1e-12f)));
        lm2[c] = pk(l0, l1);
        ph2[c] = pk(atan2f(i0, r0), atan2f(i1, r1));
    }
    #pragma unroll
    for (int o = 0; o < C16; o++) {
        ull sr = sbr2[o], si = sbi2[o];
        #pragma unroll
        for (int c = 0; c < C8; c++) {
            sr = ffma2(swr2[o*C8+c], lm2[c], sr);
            si = ffma2(swi2[o*C8+c], ph2[c], si);
        }
        float s0, s1, p0, p1;
        upk(sr, s0, s1); upk(si, p0, p1);
        float w0 = (__cosf(p0) + 1.0f) * 0.5f;
        float w1 = (__cosf(p1) + 1.0f) * 0.5f;
        st64(g_s1 + ((b*2+0)*C16 + o)*CHW + off, pk(w0*s0, w1*s1));
        st64(g_s1 + ((b*2+1)*C16 + o)*CHW + off, pk(mod2pi(p0), mod2pi(p1)));
    }
}

// ---------------------------------------------------------------------------
// Kernel B: freq_conv (depthwise over freq, k=5, pad=2) -> cAct. 2 t/thread.
// ---------------------------------------------------------------------------
__global__ void kB(const float* __restrict__ wr, const float* __restrict__ wi,
                   const float* __restrict__ br, const float* __restrict__ bi)
{
    const int f  = blockIdx.y;
    const int bc = blockIdx.z;
    const int b  = bc / C16;
    const int c  = bc % C16;
    const int tp = 2 * (blockIdx.x * blockDim.x + threadIdx.x);
    if (tp >= TN) return;

    const int base_r = ((b*2+0)*C16 + c)*CHW;
    const int base_i = ((b*2+1)*C16 + c)*CHW;

    float b_r = br[c], b_i = bi[c];
    ull yr = pk(b_r, b_r);
    ull yi = pk(b_i, b_i);
    #pragma unroll
    for (int j = 0; j < 5; j++) {
        int ff = f + j - 2;
        if (ff >= 0 && ff < FF) {
            float a = wr[c*5 + j]; float d = wi[c*5 + j];
            yr = ffma2(pk(a, a), ld64(g_s1 + base_r + ff*TN + tp), yr);
            yi = ffma2(pk(d, d), ld64(g_s1 + base_i + ff*TN + tp), yi);
        }
    }
    float r0, r1, i0, i1;
    upk(yr, r0, r1); upk(yi, i0, i1);
    float w0 = (__cosf(i0) + 1.0f) * 0.5f;
    float w1 = (__cosf(i1) + 1.0f) * 0.5f;
    st64(g_s2 + base_r + f*TN + tp, pk(w0*r0, w1*r1));
    st64(g_s2 + base_i + f*TN + tp, pk(mod2pi(i0), mod2pi(i1)));
}

// ---------------------------------------------------------------------------
// Kernel C: time_conv (16->8, taps t+2k) -> cExp -> last_shuffle(complex)
//           -> cMul(x) -> last(complex) -> out.  2 timesteps per thread.
// ---------------------------------------------------------------------------
__global__ void kC(
    const float* __restrict__ x,
    const float* __restrict__ twr, const float* __restrict__ twi,
    const float* __restrict__ tbr, const float* __restrict__ tbi,
    const float* __restrict__ lwr, const float* __restrict__ lwi,
    const float* __restrict__ lbr, const float* __restrict__ lbi,
    const float* __restrict__ awr, const float* __restrict__ awi,
    const float* __restrict__ abr, const float* __restrict__ abi,
    float* __restrict__ out)
{
    const int f = blockIdx.x & (FF-1);
    const int b = blockIdx.x >> 8;

    __shared__ ull stwr2[C8*C16*5], stwi2[C8*C16*5];       // (o*16+c)*5+k, packed (w,w)
    __shared__ ull slwr2[64], slwi2[64], nlwi2[64];        // ls weights, +neg wi
    __shared__ ull sawr2[64], sawi2[64], nawi2[64];        // la weights
    __shared__ ull stbr2[8], stbi2[8];
    __shared__ ull slbd2[8], slbs2[8];                      // (br-bi), (br+bi)
    __shared__ ull sabd2[8], sabs2[8];

    for (int i = threadIdx.x; i < C8*C16*5; i += blockDim.x) {
        float a = twr[f*C8*C16*5 + i]; stwr2[i] = pk(a, a);
        float c = twi[f*C8*C16*5 + i]; stwi2[i] = pk(c, c);
    }
    if (threadIdx.x < 64) {
        float a = lwr[f*64 + threadIdx.x]; slwr2[threadIdx.x] = pk(a, a);
        float c = lwi[f*64 + threadIdx.x]; slwi2[threadIdx.x] = pk(c, c);
        nlwi2[threadIdx.x] = pk(-c, -c);
        float d = awr[f*64 + threadIdx.x]; sawr2[threadIdx.x] = pk(d, d);
        float e = awi[f*64 + threadIdx.x]; sawi2[threadIdx.x] = pk(e, e);
        nawi2[threadIdx.x] = pk(-e, -e);
    }
    if (threadIdx.x < 8) {
        float a = tbr[f*8 + threadIdx.x], c = tbi[f*8 + threadIdx.x];
        stbr2[threadIdx.x] = pk(a, a); stbi2[threadIdx.x] = pk(c, c);
        float d = lbr[f*8 + threadIdx.x], e = lbi[f*8 + threadIdx.x];
        slbd2[threadIdx.x] = pk(d - e, d - e); slbs2[threadIdx.x] = pk(d + e, d + e);
        float g = abr[f*8 + threadIdx.x], h = abi[f*8 + threadIdx.x];
        sabd2[threadIdx.x] = pk(g - h, g - h); sabs2[threadIdx.x] = pk(g + h, g + h);
    }
    __syncthreads();

    const float* s2r  = g_s2 + (b*2+0)*C16*CHW + f*TN;
    const float* s2i  = g_s2 + (b*2+1)*C16*CHW + f*TN;
    const float* xr_p = x    + (b*2+0)*C8 *CHW + f*TN;
    const float* xi_p = x    + (b*2+1)*C8 *CHW + f*TN;
    float* outr = out + (b*2+0)*C8*CHW + f*TN;
    float* outi = out + (b*2+1)*C8*CHW + f*TN;

    for (int tp = 2*threadIdx.x; tp < TN; tp += 2*blockDim.x) {
        // ---- time_conv ----
        ull ar2[8], ai2[8];
        #pragma unroll
        for (int o = 0; o < 8; o++) { ar2[o] = stbr2[o]; ai2[o] = stbi2[o]; }

        if (tp + 9 < TN) {                    // all taps in range for both lanes
            #pragma unroll
            for (int k = 0; k < 5; k++) {
                #pragma unroll
                for (int c = 0; c < C16; c++) {
                    ull vr = ld64(s2r + c*CHW + tp + 2*k);
                    ull vi = ld64(s2i + c*CHW + tp + 2*k);
                    #pragma unroll
                    for (int o = 0; o < 8; o++) {
                        ar2[o] = ffma2(stwr2[(o*C16 + c)*5 + k], vr, ar2[o]);
                        ai2[o] = ffma2(stwi2[(o*C16 + c)*5 + k], vi, ai2[o]);
                    }
                }
            }
        } else {                               // boundary: scalar per-lane with guard
            float arL[8], aiL[8], arH[8], aiH[8];
            #pragma unroll
            for (int o = 0; o < 8; o++) {
                float lo, hi;
                upk(ar2[o], lo, hi); arL[o] = lo; arH[o] = hi;
                upk(ai2[o], lo, hi); aiL[o] = lo; aiH[o] = hi;
            }
            for (int k = 0; k < 5; k++) {
                int t0 = tp + 2*k, t1 = tp + 1 + 2*k;
                for (int c = 0; c < C16; c++) {
                    float vr0 = (t0 < TN) ? s2r[c*CHW + t0] : 0.0f;
                    float vi0 = (t0 < TN) ? s2i[c*CHW + t0] : 0.0f;
                    float vr1 = (t1 < TN) ? s2r[c*CHW + t1] : 0.0f;
                    float vi1 = (t1 < TN) ? s2i[c*CHW + t1] : 0.0f;
                    for (int o = 0; o < 8; o++) {
                        float wr_ = ((const float*)&stwr2[(o*C16 + c)*5 + k])[0];
                        float wi_ = ((const float*)&stwi2[(o*C16 + c)*5 + k])[0];
                        arL[o] = fmaf(wr_, vr0, arL[o]);
                        aiL[o] = fmaf(wi_, vi0, aiL[o]);
                        arH[o] = fmaf(wr_, vr1, arH[o]);
                        aiH[o] = fmaf(wi_, vi1, aiH[o]);
                    }
                }
            }
            #pragma unroll
            for (int o = 0; o < 8; o++) {
                ar2[o] = pk(arL[o], arH[o]);
                ai2[o] = pk(aiL[o], aiH[o]);
            }
        }

        // ---- cExp ----
        ull er2[8], ei2[8];
        #pragma unroll
        for (int o = 0; o < 8; o++) {
            float a0, a1, p0, p1;
            upk(ar2[o], a0, a1); upk(ai2[o], p0, p1);
            float r0 = __expf(a0), r1 = __expf(a1);
            float sn0, cs0, sn1, cs1;
            __sincosf(p0, &sn0, &cs0);
            __sincosf(p1, &sn1, &cs1);
            er2[o] = pk(r0*cs0, r1*cs1);
            ei2[o] = pk(r0*sn0, r1*sn1);
        }

        // ---- last_shuffle (complex 8x8) ----
        ull sr2[8], si2[8];
        #pragma unroll
        for (int o = 0; o < 8; o++) {
            ull yr = slbd2[o], yi = slbs2[o];
            #pragma unroll
            for (int c = 0; c < 8; c++) {
                yr = ffma2(slwr2[o*8+c], er2[c], yr);
                yr = ffma2(nlwi2[o*8+c], ei2[c], yr);
                yi = ffma2(slwr2[o*8+c], ei2[c], yi);
                yi = ffma2(slwi2[o*8+c], er2[c], yi);
            }
            sr2[o] = yr; si2[o] = yi;
        }

        // ---- cMul with x ----
        ull mr2[8], mi2[8];
        #pragma unroll
        for (int c = 0; c < 8; c++) {
            ull vxr = ld64(xr_p + c*CHW + tp);
            ull vxi = ld64(xi_p + c*CHW + tp);
            ull nsi = fmul2(si2[c], pk(-1.0f, -1.0f));
            mr2[c] = ffma2(sr2[c], vxr, fmul2(nsi, vxi));
            mi2[c] = ffma2(sr2[c], vxi, fmul2(si2[c], vxr));
        }

        // ---- last (complex 8x8) -> out ----
        #pragma unroll
        for (int o = 0; o < 8; o++) {
            ull yr = sabd2[o], yi = sabs2[o];
            #pragma unroll
            for (int c = 0; c < 8; c++) {
                yr = ffma2(sawr2[o*8+c], mr2[c], yr);
                yr = ffma2(nawi2[o*8+c], mi2[c], yr);
                yi = ffma2(sawr2[o*8+c], mi2[c], yi);
                yi = ffma2(sawi2[o*8+c], mr2[c], yi);
            }
            st64(outr + o*CHW + tp, yr);
            st64(outi + o*CHW + tp, yi);
        }
    }
}

// ---------------------------------------------------------------------------
extern "C" void kernel_launch(void* const* d_in, const int* in_sizes, int n_in,
                              void* d_out, int out_size)
{
    const float* x     = (const float*)d_in[0];
    const float* cs_wr = (const float*)d_in[1];
    const float* cs_wi = (const float*)d_in[2];
    const float* cs_br = (const float*)d_in[3];
    const float* cs_bi = (const float*)d_in[4];
    const float* fc_wr = (const float*)d_in[5];
    const float* fc_wi = (const float*)d_in[6];
    const float* fc_br = (const float*)d_in[7];
    const float* fc_bi = (const float*)d_in[8];
    const float* tc_wr = (const float*)d_in[9];
    const float* tc_wi = (const float*)d_in[10];
    const float* tc_br = (const float*)d_in[11];
    const float* tc_bi = (const float*)d_in[12];
    const float* ls_wr = (const float*)d_in[13];
    const float* ls_wi = (const float*)d_in[14];
    const float* ls_br = (const float*)d_in[15];
    const float* ls_bi = (const float*)d_in[16];
    const float* la_wr = (const float*)d_in[17];
    const float* la_wi = (const float*)d_in[18];
    const float* la_br = (const float*)d_in[19];
    const float* la_bi = (const float*)d_in[20];
    float* out = (float*)d_out;

    dim3 gA((TN/2 + 255)/256, FF, BB);
    kA<<<gA, 256>>>(x, cs_wr, cs_wi, cs_br, cs_bi);

    dim3 gB((TN/2 + 255)/256, FF, BB*C16);
    kB<<<gB, 256>>>(fc_wr, fc_wi, fc_br, fc_bi);

    kC<<<BB*FF, 256>>>(x, tc_wr, tc_wi, tc_br, tc_bi,
                       ls_wr, ls_wi, ls_br, ls_bi,
                       la_wr, la_wi, la_br, la_bi, out);
}

// round 3
// speedup vs baseline: 2.2577x; 2.2577x over previous
#include <cuda_runtime.h>
#include <math.h>

#define BB   4
#define C8   8
#define C16  16
#define FF   256
#define TN   2000
#define CHW  (FF*TN)
#define TWO_PI_F     6.283185307179586f
#define INV_TWO_PI_F 0.15915494309189535f

typedef unsigned long long ull;

__device__ float g_s1[BB*2*C16*CHW];
__device__ float g_s2[BB*2*C16*CHW];

__device__ __forceinline__ float mod2pi(float a) {
    return a - floorf(a * INV_TWO_PI_F) * TWO_PI_F;
}

// ---- f32x2 helpers (used in kA/kB only) ----
__device__ __forceinline__ ull pk(float lo, float hi) {
    ull r; asm("mov.b64 %0,{%1,%2};" : "=l"(r) : "f"(lo), "f"(hi)); return r;
}
__device__ __forceinline__ void upk(ull v, float& lo, float& hi) {
    asm("mov.b64 {%0,%1},%2;" : "=f"(lo), "=f"(hi) : "l"(v));
}
__device__ __forceinline__ ull ffma2(ull a, ull b, ull c) {
    ull d; asm("fma.rn.f32x2 %0,%1,%2,%3;" : "=l"(d) : "l"(a), "l"(b), "l"(c)); return d;
}
__device__ __forceinline__ ull ld64(const float* p) {
    return *reinterpret_cast<const ull*>(p);
}
__device__ __forceinline__ void st64(float* p, ull v) {
    *reinterpret_cast<ull*>(p) = v;
}

// ---------------------------------------------------------------------------
// Kernel A: cLog -> channel_shuffle (8->16) -> cAct.  2 timesteps per thread.
// ---------------------------------------------------------------------------
__global__ void kA(const float* __restrict__ x,
                   const float* __restrict__ wr, const float* __restrict__ wi,
                   const float* __restrict__ br, const float* __restrict__ bi)
{
    const int f = blockIdx.y;
    const int b = blockIdx.z;

    __shared__ ull swr2[C16*C8], swi2[C16*C8];
    __shared__ ull sbr2[C16], sbi2[C16];
    for (int i = threadIdx.x; i < C16*C8; i += blockDim.x) {
        float a = wr[f*C16*C8 + i]; swr2[i] = pk(a, a);
        float c = wi[f*C16*C8 + i]; swi2[i] = pk(c, c);
    }
    if (threadIdx.x < C16) {
        float a = br[f*C16 + threadIdx.x]; sbr2[threadIdx.x] = pk(a, a);
        float c = bi[f*C16 + threadIdx.x]; sbi2[threadIdx.x] = pk(c, c);
    }
    __syncthreads();

    const int tp = 2 * (blockIdx.x * blockDim.x + threadIdx.x);
    if (tp >= TN) return;
    const int off = f*TN + tp;

    ull lm2[C8], ph2[C8];
    #pragma unroll
    for (int c = 0; c < C8; c++) {
        ull xr = ld64(x + ((b*2+0)*C8 + c)*CHW + off);
        ull xi = ld64(x + ((b*2+1)*C8 + c)*CHW + off);
        float r0, r1, i0, i1;
        upk(xr, r0, r1); upk(xi, i0, i1);
        float l0 = 0.5f * __logf(fmaf(r0, r0, fmaf(i0, i0, 1e-12f)));
        float l1 = 0.5f * __logf(fmaf(r1, r1, fmaf(i1, i1, 1e-12f)));
        lm2[c] = pk(l0, l1);
        ph2[c] = pk(atan2f(i0, r0), atan2f(i1, r1));
    }
    #pragma unroll
    for (int o = 0; o < C16; o++) {
        ull sr = sbr2[o], si = sbi2[o];
        #pragma unroll
        for (int c = 0; c < C8; c++) {
            sr = ffma2(swr2[o*C8+c], lm2[c], sr);
            si = ffma2(swi2[o*C8+c], ph2[c], si);
        }
        float s0, s1, p0, p1;
        upk(sr, s0, s1); upk(si, p0, p1);
        float w0 = (__cosf(p0) + 1.0f) * 0.5f;
        float w1 = (__cosf(p1) + 1.0f) * 0.5f;
        st64(g_s1 + ((b*2+0)*C16 + o)*CHW + off, pk(w0*s0, w1*s1));
        st64(g_s1 + ((b*2+1)*C16 + o)*CHW + off, pk(mod2pi(p0), mod2pi(p1)));
    }
}

// ---------------------------------------------------------------------------
// Kernel B: freq_conv (depthwise over freq, k=5, pad=2) -> cAct. 2 t/thread.
// ---------------------------------------------------------------------------
__global__ void kB(const float* __restrict__ wr, const float* __restrict__ wi,
                   const float* __restrict__ br, const float* __restrict__ bi)
{
    const int f  = blockIdx.y;
    const int bc = blockIdx.z;
    const int b  = bc / C16;
    const int c  = bc % C16;
    const int tp = 2 * (blockIdx.x * blockDim.x + threadIdx.x);
    if (tp >= TN) return;

    const int base_r = ((b*2+0)*C16 + c)*CHW;
    const int base_i = ((b*2+1)*C16 + c)*CHW;

    float b_r = br[c], b_i = bi[c];
    ull yr = pk(b_r, b_r);
    ull yi = pk(b_i, b_i);
    #pragma unroll
    for (int j = 0; j < 5; j++) {
        int ff = f + j - 2;
        if (ff >= 0 && ff < FF) {
            float a = wr[c*5 + j]; float d = wi[c*5 + j];
            yr = ffma2(pk(a, a), ld64(g_s1 + base_r + ff*TN + tp), yr);
            yi = ffma2(pk(d, d), ld64(g_s1 + base_i + ff*TN + tp), yi);
        }
    }
    float r0, r1, i0, i1;
    upk(yr, r0, r1); upk(yi, i0, i1);
    float w0 = (__cosf(i0) + 1.0f) * 0.5f;
    float w1 = (__cosf(i1) + 1.0f) * 0.5f;
    st64(g_s2 + base_r + f*TN + tp, pk(w0*r0, w1*r1));
    st64(g_s2 + base_i + f*TN + tp, pk(mod2pi(i0), mod2pi(i1)));
}

// ---------------------------------------------------------------------------
// Kernel C: time_conv (16->8, taps t+2k) -> cExp -> ls(complex) -> cMul(x)
//           -> la(complex) -> out.  2 t/thread, scalar FFMA, LDS.128 weights.
// Weight layout in shared: stwr[(c*5+k)*8 + o]  -> uniform LDS.128 per (c,k).
// ---------------------------------------------------------------------------
template<bool FULL>
__device__ __forceinline__ void tc_core(
    const float* __restrict__ s2r, const float* __restrict__ s2i,
    const float* __restrict__ stwr, const float* __restrict__ stwi,
    int t0, float ar[8][2], float ai[8][2])
{
    #pragma unroll
    for (int c = 0; c < C16; c++) {
        float vr[10], vi[10];
        if (FULL) {
            #pragma unroll
            for (int m = 0; m < 5; m++) {
                float2 a = *reinterpret_cast<const float2*>(s2r + c*CHW + t0 + 2*m);
                float2 d = *reinterpret_cast<const float2*>(s2i + c*CHW + t0 + 2*m);
                vr[2*m] = a.x; vr[2*m+1] = a.y;
                vi[2*m] = d.x; vi[2*m+1] = d.y;
            }
        } else {
            #pragma unroll
            for (int j = 0; j < 10; j++) {
                int tt = t0 + j;
                vr[j] = (tt < TN) ? s2r[c*CHW + tt] : 0.0f;
                vi[j] = (tt < TN) ? s2i[c*CHW + tt] : 0.0f;
            }
        }
        #pragma unroll
        for (int k = 0; k < 5; k++) {
            const float4 wr0 = *reinterpret_cast<const float4*>(stwr + (c*5+k)*8);
            const float4 wr1 = *reinterpret_cast<const float4*>(stwr + (c*5+k)*8 + 4);
            const float4 wi0 = *reinterpret_cast<const float4*>(stwi + (c*5+k)*8);
            const float4 wi1 = *reinterpret_cast<const float4*>(stwi + (c*5+k)*8 + 4);
            const float wrs[8] = {wr0.x, wr0.y, wr0.z, wr0.w, wr1.x, wr1.y, wr1.z, wr1.w};
            const float wis[8] = {wi0.x, wi0.y, wi0.z, wi0.w, wi1.x, wi1.y, wi1.z, wi1.w};
            #pragma unroll
            for (int o = 0; o < 8; o++) {
                ar[o][0] = fmaf(wrs[o], vr[2*k],   ar[o][0]);
                ar[o][1] = fmaf(wrs[o], vr[2*k+1], ar[o][1]);
                ai[o][0] = fmaf(wis[o], vi[2*k],   ai[o][0]);
                ai[o][1] = fmaf(wis[o], vi[2*k+1], ai[o][1]);
            }
        }
    }
}

__global__ void __launch_bounds__(256) kC(
    const float* __restrict__ x,
    const float* __restrict__ twr, const float* __restrict__ twi,
    const float* __restrict__ tbr, const float* __restrict__ tbi,
    const float* __restrict__ lwr, const float* __restrict__ lwi,
    const float* __restrict__ lbr, const float* __restrict__ lbi,
    const float* __restrict__ awr, const float* __restrict__ awi,
    const float* __restrict__ abr, const float* __restrict__ abi,
    float* __restrict__ out)
{
    const int f = blockIdx.x & (FF-1);
    const int b = blockIdx.x >> 8;

    __shared__ __align__(16) float stwr[C8*C16*5], stwi[C8*C16*5];  // [(c*5+k)*8+o]
    __shared__ float slwr[64], slwi[64], sawr[64], sawi[64];        // [o*8+c]
    __shared__ float stbr[8], stbi[8], slbr[8], slbi[8], sabr[8], sabi[8];

    for (int i = threadIdx.x; i < C8*C16*5; i += blockDim.x) {
        int o = i & 7, ck = i >> 3;
        int c = ck / 5, k = ck - 5*c;
        stwr[i] = twr[f*C8*C16*5 + (o*C16 + c)*5 + k];
        stwi[i] = twi[f*C8*C16*5 + (o*C16 + c)*5 + k];
    }
    if (threadIdx.x < 64) {
        slwr[threadIdx.x] = lwr[f*64 + threadIdx.x];
        slwi[threadIdx.x] = lwi[f*64 + threadIdx.x];
        sawr[threadIdx.x] = awr[f*64 + threadIdx.x];
        sawi[threadIdx.x] = awi[f*64 + threadIdx.x];
    }
    if (threadIdx.x < 8) {
        stbr[threadIdx.x] = tbr[f*8 + threadIdx.x];
        stbi[threadIdx.x] = tbi[f*8 + threadIdx.x];
        slbr[threadIdx.x] = lbr[f*8 + threadIdx.x];
        slbi[threadIdx.x] = lbi[f*8 + threadIdx.x];
        sabr[threadIdx.x] = abr[f*8 + threadIdx.x];
        sabi[threadIdx.x] = abi[f*8 + threadIdx.x];
    }
    __syncthreads();

    const float* s2r  = g_s2 + (b*2+0)*C16*CHW + f*TN;
    const float* s2i  = g_s2 + (b*2+1)*C16*CHW + f*TN;
    const float* xr_p = x    + (b*2+0)*C8 *CHW + f*TN;
    const float* xi_p = x    + (b*2+1)*C8 *CHW + f*TN;
    float* outr = out + (b*2+0)*C8*CHW + f*TN;
    float* outi = out + (b*2+1)*C8*CHW + f*TN;

    for (int t0 = 2*threadIdx.x; t0 < TN; t0 += 2*blockDim.x) {
        float ar[8][2], ai[8][2];
        #pragma unroll
        for (int o = 0; o < 8; o++) {
            ar[o][0] = stbr[o]; ar[o][1] = stbr[o];
            ai[o][0] = stbi[o]; ai[o][1] = stbi[o];
        }

        if (t0 + 9 < TN) tc_core<true >(s2r, s2i, stwr, stwi, t0, ar, ai);
        else             tc_core<false>(s2r, s2i, stwr, stwi, t0, ar, ai);

        float orj[8][2], oij[8][2];
        #pragma unroll
        for (int j = 0; j < 2; j++) {
            // cExp
            float er[8], ei[8];
            #pragma unroll
            for (int o = 0; o < 8; o++) {
                float r = __expf(ar[o][j]);
                float sn, cs;
                __sincosf(ai[o][j], &sn, &cs);
                er[o] = r * cs;
                ei[o] = r * sn;
            }
            // last_shuffle (complex 8x8)
            float sr[8], si[8];
            #pragma unroll
            for (int o = 0; o < 8; o++) {
                float yr = slbr[o] - slbi[o];
                float yi = slbr[o] + slbi[o];
                #pragma unroll
                for (int c = 0; c < 8; c++) {
                    float wr_ = slwr[o*8+c], wi_ = slwi[o*8+c];
                    yr = fmaf(wr_, er[c], yr);
                    yr = fmaf(-wi_, ei[c], yr);
                    yi = fmaf(wr_, ei[c], yi);
                    yi = fmaf(wi_, er[c], yi);
                }
                sr[o] = yr; si[o] = yi;
            }
            // cMul with x
            float mr[8], mi[8];
            #pragma unroll
            for (int c = 0; c < 8; c++) {
                float vxr = xr_p[c*CHW + t0 + j];
                float vxi = xi_p[c*CHW + t0 + j];
                mr[c] = sr[c]*vxr - si[c]*vxi;
                mi[c] = sr[c]*vxi + si[c]*vxr;
            }
            // last (complex 8x8)
            #pragma unroll
            for (int o = 0; o < 8; o++) {
                float yr = sabr[o] - sabi[o];
                float yi = sabr[o] + sabi[o];
                #pragma unroll
                for (int c = 0; c < 8; c++) {
                    float wr_ = sawr[o*8+c], wi_ = sawi[o*8+c];
                    yr = fmaf(wr_, mr[c], yr);
                    yr = fmaf(-wi_, mi[c], yr);
                    yi = fmaf(wr_, mi[c], yi);
                    yi = fmaf(wi_, mr[c], yi);
                }
                orj[o][j] = yr; oij[o][j] = yi;
            }
        }
        #pragma unroll
        for (int o = 0; o < 8; o++) {
            *reinterpret_cast<float2*>(outr + o*CHW + t0) = make_float2(orj[o][0], orj[o][1]);
            *reinterpret_cast<float2*>(outi + o*CHW + t0) = make_float2(oij[o][0], oij[o][1]);
        }
    }
}

// ---------------------------------------------------------------------------
extern "C" void kernel_launch(void* const* d_in, const int* in_sizes, int n_in,
                              void* d_out, int out_size)
{
    const float* x     = (const float*)d_in[0];
    const float* cs_wr = (const float*)d_in[1];
    const float* cs_wi = (const float*)d_in[2];
    const float* cs_br = (const float*)d_in[3];
    const float* cs_bi = (const float*)d_in[4];
    const float* fc_wr = (const float*)d_in[5];
    const float* fc_wi = (const float*)d_in[6];
    const float* fc_br = (const float*)d_in[7];
    const float* fc_bi = (const float*)d_in[8];
    const float* tc_wr = (const float*)d_in[9];
    const float* tc_wi = (const float*)d_in[10];
    const float* tc_br = (const float*)d_in[11];
    const float* tc_bi = (const float*)d_in[12];
    const float* ls_wr = (const float*)d_in[13];
    const float* ls_wi = (const float*)d_in[14];
    const float* ls_br = (const float*)d_in[15];
    const float* ls_bi = (const float*)d_in[16];
    const float* la_wr = (const float*)d_in[17];
    const float* la_wi = (const float*)d_in[18];
    const float* la_br = (const float*)d_in[19];
    const float* la_bi = (const float*)d_in[20];
    float* out = (float*)d_out;

    dim3 gA((TN/2 + 255)/256, FF, BB);
    kA<<<gA, 256>>>(x, cs_wr, cs_wi, cs_br, cs_bi);

    dim3 gB((TN/2 + 255)/256, FF, BB*C16);
    kB<<<gB, 256>>>(fc_wr, fc_wi, fc_br, fc_bi);

    kC<<<BB*FF, 256>>>(x, tc_wr, tc_wi, tc_br, tc_bi,
                       ls_wr, ls_wi, ls_br, ls_bi,
                       la_wr, la_wi, la_br, la_bi, out);
}